// round 14
// baseline (speedup 1.0000x reference)
#include <cuda_runtime.h>
#include <cuda_fp16.h>
#include <math.h>
#include <cstdint>

#define H 1024
#define H2 512                 // H in half2 words
#define NEXP 16
#define TOPK 6
#define EPS 1e-10f
#define MAXT 8192
#define SEG 8192

// GEMM: persistent CTAs, CTA tile 128x128, K-tile 64 halves, fp16 m16n8k16,
// 128 threads (2x2 warps of 64x64), 3 rotating stages, 2 CTAs/SM.
#define BM 128
#define BN 128
#define BKW 32                 // K-tile in half2 words (= 64 halves)
#define NKT (H2 / BKW)         // 16
#define STG 3
#define AST 36                 // A row stride words (32 data + 4 pad)
#define BSTRIDE 136            // B row stride words (128 data + 8 pad)
#define A_BYTES (BM * AST * 4)           // 18432
#define B_BYTES (BKW * BSTRIDE * 4)      // 17408
#define STAGE_BYTES (A_BYTES + B_BYTES)  // 35840
#define SM_TOKBUF (STG * STAGE_BYTES)    // 107520 : int tok[2][128]
#define SM_WBUF (SM_TOKBUF + 1024)       // float w[2][128]
#define SM_TOTAL (SM_WBUF + 1024)        // 109568 (x2 CTAs = 219KB)

#define GRID_GEMM 296          // 2 per SM (148 SMs)
#define NTILES_MAX 512

// ---------------- device scratch ----------------
__device__ int     g_cursor[NEXP];
__device__ int     g_nwork;
__device__ int     g_tile_e[NTILES_MAX];
__device__ int     g_tile_m[NTILES_MAX];
__device__ int     g_tile_c[NTILES_MAX];
__device__ float   g_sw[MAXT];
__device__ int     g_pair_token[NEXP * SEG];
__device__ float   g_pairw[NEXP * SEG];
__device__ int     g_pos[MAXT * TOPK];
__device__ __half2 g_Yp[(size_t)NEXP * SEG * H2];   // expert outputs (fp16)
__device__ __half2 g_Wt[(size_t)NEXP * H2 * H];     // W packed [e][k/2][n]
__device__ __half2 g_Xt[(size_t)MAXT * H2];         // X packed [t][k/2]

// ---------------- helpers ----------------
__device__ __forceinline__ uint32_t s2u(const void* p) {
    uint32_t a;
    asm("{ .reg .u64 t; cvta.to.shared.u64 t, %1; cvt.u32.u64 %0, t; }"
        : "=r"(a) : "l"(p));
    return a;
}
__device__ __forceinline__ void cpa16(uint32_t dst, const void* src) {
    asm volatile("cp.async.cg.shared.global [%0], [%1], 16;" :: "r"(dst), "l"(src));
}
__device__ __forceinline__ void cpa_commit() {
    asm volatile("cp.async.commit_group;" ::: "memory");
}
__device__ __forceinline__ void cpa_wait1() {
    asm volatile("cp.async.wait_group 1;" ::: "memory");
}
__device__ __forceinline__ void mma16(float* c, const unsigned* a, const unsigned* b) {
    asm volatile(
        "mma.sync.aligned.m16n8k16.row.col.f32.f16.f16.f32 "
        "{%0,%1,%2,%3}, {%4,%5,%6,%7}, {%8,%9}, {%0,%1,%2,%3};"
        : "+f"(c[0]), "+f"(c[1]), "+f"(c[2]), "+f"(c[3])
        : "r"(a[0]), "r"(a[1]), "r"(a[2]), "r"(a[3]), "r"(b[0]), "r"(b[1]));
}

// ---------------- pack W (+ reset cursors): g_Wt[e][k/2][n] ----------------
__global__ void cvt_w_kernel(const float* __restrict__ src) {
    if (blockIdx.x == 0 && threadIdx.x < NEXP) g_cursor[threadIdx.x] = 0;
    int idx = blockIdx.x * blockDim.x + threadIdx.x;
    if (idx >= NEXP * H2 * H) return;
    int n = idx & (H - 1);
    int kpg = idx >> 10;
    int e = kpg >> 9;
    int kp = kpg & (H2 - 1);
    size_t so = ((size_t)e * H + 2 * kp) * H + n;
    g_Wt[idx] = __floats2half2_rn(src[so], src[so + H]);
}

// ---------------- scan: exact tile table ----------------
__global__ void scan_kernel() {
    if (threadIdx.x == 0) {
        int tiles = 0;
        for (int e = 0; e < NEXP; ++e) {
            int cnt = g_cursor[e];
            for (int m = 0; m < cnt; m += BM) {
                g_tile_e[tiles] = e;
                g_tile_m[tiles] = m;
                g_tile_c[tiles] = cnt;
                ++tiles;
            }
        }
        g_nwork = tiles * (H / BN);
    }
}

// ---------------- router: 2 tokens per warp; packs X to fp16 and scatters ----------------
__global__ void router_kernel(const float* __restrict__ x,
                              const float* __restrict__ rw,
                              const float* __restrict__ rb, int T) {
    extern __shared__ float s_rw[];

    int tid = threadIdx.x;
    for (int i = tid; i < NEXP * H; i += blockDim.x) s_rw[i] = rw[i];
    __syncthreads();

    int warp = tid >> 5, lane = tid & 31;
    int t0 = (blockIdx.x * (blockDim.x >> 5) + warp) * 2;
    if (t0 >= T) return;

    const float2* xr0 = (const float2*)(x + (size_t)t0 * H);
    const float2* xr1 = (const float2*)(x + (size_t)(t0 + 1) * H);

    float acc0[NEXP], acc1[NEXP];
    #pragma unroll
    for (int e = 0; e < NEXP; ++e) { acc0[e] = 0.f; acc1[e] = 0.f; }
    for (int ii = lane; ii < H2; ii += 32) {
        float2 v0 = xr0[ii], v1 = xr1[ii];
        g_Xt[(size_t)t0 * H2 + ii]       = __floats2half2_rn(v0.x, v0.y);
        g_Xt[(size_t)(t0 + 1) * H2 + ii] = __floats2half2_rn(v1.x, v1.y);
        #pragma unroll
        for (int e = 0; e < NEXP; ++e) {
            float2 w = ((const float2*)(s_rw + e * H))[ii];
            acc0[e] += v0.x * w.x + v0.y * w.y;
            acc1[e] += v1.x * w.x + v1.y * w.y;
        }
    }

    #pragma unroll
    for (int tk = 0; tk < 2; ++tk) {
        int t = t0 + tk;
        float logit;
        {
            float a[NEXP];
            #pragma unroll
            for (int e = 0; e < NEXP; ++e) a[e] = tk ? acc1[e] : acc0[e];
            #pragma unroll
            for (int e = 0; e < NEXP; ++e) {
                #pragma unroll
                for (int o = 16; o > 0; o >>= 1)
                    a[e] += __shfl_xor_sync(0xffffffffu, a[e], o);
            }
            logit = (lane < NEXP) ? (a[lane] + rb[lane]) : -INFINITY;
        }

        float mx = logit;
        #pragma unroll
        for (int o = 16; o > 0; o >>= 1)
            mx = fmaxf(mx, __shfl_xor_sync(0xffffffffu, mx, o));
        float p = (lane < NEXP) ? expf(logit - mx) : 0.f;
        float sum = p;
        #pragma unroll
        for (int o = 16; o > 0; o >>= 1)
            sum += __shfl_xor_sync(0xffffffffu, sum, o);
        float prob = p / sum;

        float cur = (lane < NEXP) ? prob : -1.f;
        float tv[TOPK]; int ti[TOPK];
        float s = 0.f;
        #pragma unroll
        for (int k = 0; k < TOPK; ++k) {
            float v = cur; int bi = lane;
            #pragma unroll
            for (int o = 16; o > 0; o >>= 1) {
                float ov = __shfl_xor_sync(0xffffffffu, v, o);
                int   oi = __shfl_xor_sync(0xffffffffu, bi, o);
                if (ov > v || (ov == v && oi < bi)) { v = ov; bi = oi; }
            }
            tv[k] = v; ti[k] = bi;
            s += v;
            if (lane == bi) cur = -1.f;
        }
        if (lane == 0) {
            float inv = 1.f / (s + EPS);
            float w[TOPK], sw = 0.f;
            #pragma unroll
            for (int k = 0; k < TOPK; ++k) { w[k] = tv[k] * inv; sw += w[k]; }
            g_sw[t] = sw;
            float isw = 1.f / sw;
            int b = t * TOPK;
            #pragma unroll
            for (int k = 0; k < TOPK; ++k) {
                int e = ti[k];
                int pos = atomicAdd(&g_cursor[e], 1);
                int row = e * SEG + pos;
                g_pair_token[row] = t;
                g_pairw[row] = w[k] * isw;
                g_pos[b + k] = row;
            }
        }
    }
}

// ---------------- persistent grouped GEMM: fp16, cross-tile pipelined ----------------
__global__ void __launch_bounds__(128, 2) gemm_kernel() {
    extern __shared__ char smem[];
    const uint32_t sb = s2u(smem);
    const int tid = threadIdx.x;
    int*   s_tok = (int*)(smem + SM_TOKBUF);   // [2][128]
    float* s_wt  = (float*)(smem + SM_WBUF);   // [2][128]

    const int nwork = g_nwork;
    int it = blockIdx.x;
    if (it >= nwork) return;

    int ce, cmb, ccnt, cn0;
    {
        int tile = it >> 3;
        ce = g_tile_e[tile]; cmb = g_tile_m[tile];
        ccnt = g_tile_c[tile]; cn0 = (it & 7) * BN;
        bool ok = (cmb + tid) < ccnt;
        s_tok[tid] = ok ? g_pair_token[ce * SEG + cmb + tid] : 0;
        s_wt[tid]  = ok ? g_pairw[ce * SEG + cmb + tid] : 0.f;
    }
    __syncthreads();

    auto issue = [&](int s, int kt, int e, int n0, int pbuf) {
        const int k0 = kt * BKW;
        uint32_t ab = sb + s * STAGE_BYTES;
        const int* tok = s_tok + pbuf * 128;
        #pragma unroll
        for (int q = 0; q < 8; ++q) {
            int idx = tid + q * 128;
            int row = idx >> 3, i = idx & 7;
            cpa16(ab + (row * AST + i * 4) * 4,
                  g_Xt + (size_t)tok[row] * H2 + k0 + i * 4);
        }
        const __half2* wb = g_Wt + (size_t)e * H2 * H + n0;
        uint32_t bb = ab + A_BYTES;
        #pragma unroll
        for (int q = 0; q < 8; ++q) {
            int idx = tid + q * 128;
            int kr = idx >> 5, i = idx & 31;
            cpa16(bb + (kr * BSTRIDE + i * 4) * 4,
                  wb + (size_t)(k0 + kr) * H + i * 4);
        }
    };

    issue(0, 0, ce, cn0, 0); cpa_commit();
    issue(1, 1, ce, cn0, 0); cpa_commit();

    const int lane = tid & 31;
    const int grp = lane >> 2, tg = lane & 3;
    const int wid = tid >> 5;
    const int wm = (wid >> 1) * 64;
    const int wn = (wid & 1) * 64;

    int cs = 0, p = 0;   // consume-stage counter, tok-buffer parity

    for (;;) {
        const int nit = it + GRID_GEMM;
        const bool has_next = nit < nwork;
        int ne = 0, nmb = 0, ncnt = 0, nn0 = 0;

        float c[4][8][4];
        #pragma unroll
        for (int mi = 0; mi < 4; ++mi)
            #pragma unroll
            for (int ni = 0; ni < 8; ++ni)
                #pragma unroll
                for (int j = 0; j < 4; ++j) c[mi][ni][j] = 0.f;

        for (int kt = 0; kt < NKT; ++kt) {
            cpa_wait1();
            __syncthreads();

            if (kt == 12 && has_next) {
                int tile = nit >> 3;
                ne = g_tile_e[tile]; nmb = g_tile_m[tile];
                ncnt = g_tile_c[tile]; nn0 = (nit & 7) * BN;
                bool ok = (nmb + tid) < ncnt;
                s_tok[(p ^ 1) * 128 + tid] = ok ? g_pair_token[ne * SEG + nmb + tid] : 0;
                s_wt[(p ^ 1) * 128 + tid]  = ok ? g_pairw[ne * SEG + nmb + tid] : 0.f;
                // visibility to issue at kt==14 via syncthreads at kt==13/14
            }
            if (kt < 14)          issue((cs + 2) % 3, kt + 2, ce, cn0, p);
            else if (has_next)    issue((cs + 2) % 3, kt - 14, ne, nn0, p ^ 1);
            cpa_commit();   // exactly one commit per kt keeps wait_group(1) aligned

            const unsigned* As = (const unsigned*)(smem + (cs % 3) * STAGE_BYTES);
            const unsigned* Bs = As + BM * AST;
            ++cs;

            #pragma unroll
            for (int kk = 0; kk < 4; ++kk) {
                const int k8 = kk * 8;
                unsigned a[4][4], b[8][2];
                #pragma unroll
                for (int mi = 0; mi < 4; ++mi) {
                    int r = wm + mi * 16 + grp;
                    a[mi][0] = As[r * AST + k8 + tg];
                    a[mi][1] = As[(r + 8) * AST + k8 + tg];
                    a[mi][2] = As[r * AST + k8 + tg + 4];
                    a[mi][3] = As[(r + 8) * AST + k8 + tg + 4];
                }
                #pragma unroll
                for (int ni = 0; ni < 8; ++ni) {
                    int cn = wn + ni * 8 + grp;
                    b[ni][0] = Bs[(k8 + tg) * BSTRIDE + cn];
                    b[ni][1] = Bs[(k8 + tg + 4) * BSTRIDE + cn];
                }
                #pragma unroll
                for (int mi = 0; mi < 4; ++mi)
                    #pragma unroll
                    for (int ni = 0; ni < 8; ++ni)
                        mma16(c[mi][ni], a[mi], b[ni]);
            }
        }

        // epilogue (overlaps next tile's in-flight stage loads)
        {
            const int base = ce * SEG + cmb;
            const float* swp = s_wt + p * 128;
            #pragma unroll
            for (int mi = 0; mi < 4; ++mi) {
                int rl0 = wm + mi * 16 + grp;
                int rl1 = rl0 + 8;
                float w0 = swp[rl0], w1 = swp[rl1];
                #pragma unroll
                for (int ni = 0; ni < 8; ++ni) {
                    int colw = (cn0 + wn + ni * 8 + tg * 2) >> 1;
                    if (cmb + rl0 < ccnt)
                        g_Yp[(size_t)(base + rl0) * H2 + colw] =
                            __floats2half2_rn(c[mi][ni][0] * w0, c[mi][ni][1] * w0);
                    if (cmb + rl1 < ccnt)
                        g_Yp[(size_t)(base + rl1) * H2 + colw] =
                            __floats2half2_rn(c[mi][ni][2] * w1, c[mi][ni][3] * w1);
                }
            }
        }

        if (!has_next) break;
        it = nit; ce = ne; cmb = nmb; ccnt = ncnt; cn0 = nn0; p ^= 1;
    }
}

// ---------------- combine: out[t] = EPS*sw + sum_k Yp[pos_k] ----------------
__global__ void combine_kernel(float* __restrict__ out, int T) {
    int t = blockIdx.x;
    int c4 = threadIdx.x;
    int b = t * TOPK;
    float bias = EPS * g_sw[t];
    int cw = c4 * 2;

    float4 acc = make_float4(bias, bias, bias, bias);
    #pragma unroll
    for (int k = 0; k < TOPK; ++k) {
        int p = g_pos[b + k];
        uint2 u = *(const uint2*)(g_Yp + (size_t)p * H2 + cw);
        float2 lo = __half22float2(*(__half2*)&u.x);
        float2 hi = __half22float2(*(__half2*)&u.y);
        acc.x += lo.x; acc.y += lo.y; acc.z += hi.x; acc.w += hi.y;
    }
    *(float4*)&out[(size_t)t * H + c4 * 4] = acc;
}

// ---------------- launch ----------------
extern "C" void kernel_launch(void* const* d_in, const int* in_sizes, int n_in,
                              void* d_out, int out_size) {
    const float* tokens = (const float*)d_in[0];
    const float* rw     = (const float*)d_in[1];
    const float* rb     = (const float*)d_in[2];
    const float* ew     = (const float*)d_in[3];
    float* out = (float*)d_out;

    int T = in_sizes[0] / H;   // 8192

    cvt_w_kernel<<<(NEXP * H2 * H + 255) / 256, 256>>>(ew);           // idx 0 (+cursor reset)

    cudaFuncSetAttribute(router_kernel,
                         cudaFuncAttributeMaxDynamicSharedMemorySize, NEXP * H * 4);
    int warps_per_blk = 8;
    int rblocks = (T / 2 + warps_per_blk - 1) / warps_per_blk;
    router_kernel<<<rblocks, warps_per_blk * 32, NEXP * H * 4>>>(tokens, rw, rb, T);  // idx 1

    scan_kernel<<<1, 32>>>();                                         // idx 2

    cudaFuncSetAttribute(gemm_kernel,
                         cudaFuncAttributeMaxDynamicSharedMemorySize, SM_TOTAL);
    gemm_kernel<<<GRID_GEMM, 128, SM_TOTAL>>>();                      // idx 3 <- profiled

    combine_kernel<<<T, 256>>>(out, T);                               // idx 4
}

// round 16
// speedup vs baseline: 1.1343x; 1.1343x over previous
#include <cuda_runtime.h>
#include <cuda_fp16.h>
#include <math.h>
#include <cstdint>

#define H 1024
#define H2 512                 // H in half2 words
#define NEXP 16
#define TOPK 6
#define EPS 1e-10f
#define MAXT 8192
#define SEG 8192

// GEMM: CTA tile 128x128, K-tile 64 halves (32 half2 words), fp16 m16n8k16,
// 128 threads (2x2 warps of 64x64), 3 smem stages, 2 CTAs/SM.
#define BM 128
#define BN 128
#define BKW 32                 // K-tile in half2 words (= 64 halves)
#define NKT (H2 / BKW)         // 16
#define STG 3
#define AST 36                 // A row stride words (32 data + 4 pad)
#define BSTRIDE 136            // B row stride words (128 data + 8 pad)
#define A_BYTES (BM * AST * 4)           // 18432
#define B_BYTES (BKW * BSTRIDE * 4)      // 17408
#define STAGE_BYTES (A_BYTES + B_BYTES)  // 35840
#define SM_TOK (STG * STAGE_BYTES)       // 107520
#define SM_W   (SM_TOK + 512)
#define SM_TOTAL (SM_W + 512)            // 108544 (x2 CTAs = 217KB)

#define NTILES_MAX 400

// ---------------- device scratch ----------------
__device__ int     g_cursor[NEXP];
__device__ int     g_ntiles;
__device__ int     g_tile_e[NTILES_MAX];
__device__ int     g_tile_m[NTILES_MAX];
__device__ int     g_tile_c[NTILES_MAX];
__device__ float   g_sw[MAXT];
__device__ int     g_pair_token[NEXP * SEG];
__device__ float   g_pairw[NEXP * SEG];
__device__ int     g_pos[MAXT * TOPK];
__device__ __half2 g_Yp[(size_t)NEXP * SEG * H2];   // expert outputs (fp16)
__device__ __half2 g_Wt[(size_t)NEXP * H2 * H];     // W packed [e][k/2][n]
__device__ __half2 g_Xt[(size_t)MAXT * H2];         // X packed [t][k/2]

// ---------------- helpers ----------------
__device__ __forceinline__ uint32_t s2u(const void* p) {
    uint32_t a;
    asm("{ .reg .u64 t; cvta.to.shared.u64 t, %1; cvt.u32.u64 %0, t; }"
        : "=r"(a) : "l"(p));
    return a;
}
__device__ __forceinline__ void cpa16(uint32_t dst, const void* src) {
    asm volatile("cp.async.cg.shared.global [%0], [%1], 16;" :: "r"(dst), "l"(src));
}
__device__ __forceinline__ void cpa_commit() {
    asm volatile("cp.async.commit_group;" ::: "memory");
}
__device__ __forceinline__ void cpa_wait1() {
    asm volatile("cp.async.wait_group 1;" ::: "memory");
}
__device__ __forceinline__ void mma16(float* c, const unsigned* a, const unsigned* b) {
    asm volatile(
        "mma.sync.aligned.m16n8k16.row.col.f32.f16.f16.f32 "
        "{%0,%1,%2,%3}, {%4,%5,%6,%7}, {%8,%9}, {%0,%1,%2,%3};"
        : "+f"(c[0]), "+f"(c[1]), "+f"(c[2]), "+f"(c[3])
        : "r"(a[0]), "r"(a[1]), "r"(a[2]), "r"(a[3]), "r"(b[0]), "r"(b[1]));
}

// ---------------- pack W (+ reset cursors): g_Wt[e][k/2][n] ----------------
__global__ void cvt_w_kernel(const float* __restrict__ src) {
    if (blockIdx.x == 0 && threadIdx.x < NEXP) g_cursor[threadIdx.x] = 0;
    int idx = blockIdx.x * blockDim.x + threadIdx.x;
    if (idx >= NEXP * H2 * H) return;
    int n = idx & (H - 1);
    int kpg = idx >> 10;
    int e = kpg >> 9;
    int kp = kpg & (H2 - 1);
    size_t so = ((size_t)e * H + 2 * kp) * H + n;
    g_Wt[idx] = __floats2half2_rn(src[so], src[so + H]);
}

// ---------------- scan: exact tile table ----------------
__global__ void scan_kernel() {
    if (threadIdx.x == 0) {
        int tiles = 0;
        for (int e = 0; e < NEXP; ++e) {
            int cnt = g_cursor[e];
            for (int m = 0; m < cnt; m += BM) {
                g_tile_e[tiles] = e;
                g_tile_m[tiles] = m;
                g_tile_c[tiles] = cnt;
                ++tiles;
            }
        }
        g_ntiles = tiles;
    }
}

// ---------------- router: 2 tokens per warp; packs X to fp16 and scatters ----------------
__global__ void router_kernel(const float* __restrict__ x,
                              const float* __restrict__ rw,
                              const float* __restrict__ rb, int T) {
    extern __shared__ float s_rw[];

    int tid = threadIdx.x;
    for (int i = tid; i < NEXP * H; i += blockDim.x) s_rw[i] = rw[i];
    __syncthreads();

    int warp = tid >> 5, lane = tid & 31;
    int t0 = (blockIdx.x * (blockDim.x >> 5) + warp) * 2;
    if (t0 >= T) return;

    const float2* xr0 = (const float2*)(x + (size_t)t0 * H);
    const float2* xr1 = (const float2*)(x + (size_t)(t0 + 1) * H);

    float acc0[NEXP], acc1[NEXP];
    #pragma unroll
    for (int e = 0; e < NEXP; ++e) { acc0[e] = 0.f; acc1[e] = 0.f; }
    for (int ii = lane; ii < H2; ii += 32) {
        float2 v0 = xr0[ii], v1 = xr1[ii];
        g_Xt[(size_t)t0 * H2 + ii]       = __floats2half2_rn(v0.x, v0.y);
        g_Xt[(size_t)(t0 + 1) * H2 + ii] = __floats2half2_rn(v1.x, v1.y);
        #pragma unroll
        for (int e = 0; e < NEXP; ++e) {
            float2 w = ((const float2*)(s_rw + e * H))[ii];
            acc0[e] += v0.x * w.x + v0.y * w.y;
            acc1[e] += v1.x * w.x + v1.y * w.y;
        }
    }

    #pragma unroll
    for (int tk = 0; tk < 2; ++tk) {
        int t = t0 + tk;
        float logit;
        {
            float a[NEXP];
            #pragma unroll
            for (int e = 0; e < NEXP; ++e) a[e] = tk ? acc1[e] : acc0[e];
            #pragma unroll
            for (int e = 0; e < NEXP; ++e) {
                #pragma unroll
                for (int o = 16; o > 0; o >>= 1)
                    a[e] += __shfl_xor_sync(0xffffffffu, a[e], o);
            }
            logit = (lane < NEXP) ? (a[lane] + rb[lane]) : -INFINITY;
        }

        float mx = logit;
        #pragma unroll
        for (int o = 16; o > 0; o >>= 1)
            mx = fmaxf(mx, __shfl_xor_sync(0xffffffffu, mx, o));
        float p = (lane < NEXP) ? expf(logit - mx) : 0.f;
        float sum = p;
        #pragma unroll
        for (int o = 16; o > 0; o >>= 1)
            sum += __shfl_xor_sync(0xffffffffu, sum, o);
        float prob = p / sum;

        float cur = (lane < NEXP) ? prob : -1.f;
        float tv[TOPK]; int ti[TOPK];
        float s = 0.f;
        #pragma unroll
        for (int k = 0; k < TOPK; ++k) {
            float v = cur; int bi = lane;
            #pragma unroll
            for (int o = 16; o > 0; o >>= 1) {
                float ov = __shfl_xor_sync(0xffffffffu, v, o);
                int   oi = __shfl_xor_sync(0xffffffffu, bi, o);
                if (ov > v || (ov == v && oi < bi)) { v = ov; bi = oi; }
            }
            tv[k] = v; ti[k] = bi;
            s += v;
            if (lane == bi) cur = -1.f;
        }
        if (lane == 0) {
            float inv = 1.f / (s + EPS);
            float w[TOPK], sw = 0.f;
            #pragma unroll
            for (int k = 0; k < TOPK; ++k) { w[k] = tv[k] * inv; sw += w[k]; }
            g_sw[t] = sw;
            float isw = 1.f / sw;
            int b = t * TOPK;
            #pragma unroll
            for (int k = 0; k < TOPK; ++k) {
                int e = ti[k];
                int pos = atomicAdd(&g_cursor[e], 1);
                int row = e * SEG + pos;
                g_pair_token[row] = t;
                g_pairw[row] = w[k] * isw;
                g_pos[b + k] = row;
            }
        }
    }
}

// ---------------- grouped GEMM: fp16, tile table, spread cp.async, frag dbuf ----------------
__global__ void __launch_bounds__(128, 2) gemm_kernel() {
    extern __shared__ char smem[];
    const int tile = blockIdx.y;
    if (tile >= g_ntiles) return;
    const int e   = g_tile_e[tile];
    const int mb  = g_tile_m[tile];
    const int cnt = g_tile_c[tile];
    const int base = e * SEG + mb;
    const int n0 = blockIdx.x * BN;

    const uint32_t sb = s2u(smem);
    const int tid = threadIdx.x;
    int*   s_tok = (int*)(smem + SM_TOK);
    float* s_w   = (float*)(smem + SM_W);

    {
        bool ok = (mb + tid) < cnt;
        s_tok[tid] = ok ? g_pair_token[base + tid] : 0;
        s_w[tid]   = ok ? g_pairw[base + tid] : 0.f;
    }
    __syncthreads();

    const __half2* wb = g_Wt + (size_t)e * H2 * H + n0;

    // full-stage issue (prologue): A 8 cp16/thread, B 8 cp16/thread
    auto issue = [&](int s, int kt) {
        const int k0 = kt * BKW;
        uint32_t ab = sb + s * STAGE_BYTES;
        #pragma unroll
        for (int q = 0; q < 8; ++q) {
            int idx = tid + q * 128;
            int row = idx >> 3, i = idx & 7;
            cpa16(ab + (row * AST + i * 4) * 4,
                  g_Xt + (size_t)s_tok[row] * H2 + k0 + i * 4);
        }
        uint32_t bb = ab + A_BYTES;
        #pragma unroll
        for (int q = 0; q < 8; ++q) {
            int idx = tid + q * 128;
            int kr = idx >> 5, i = idx & 31;
            cpa16(bb + (kr * BSTRIDE + i * 4) * 4,
                  wb + (size_t)(k0 + kr) * H + i * 4);
        }
    };
    // quarter-stage issue: 2 A + 2 B cp16 per thread (chunk q = 0..3)
    auto issue_q = [&](int s, int kt, int q) {
        const int k0 = kt * BKW;
        uint32_t ab = sb + s * STAGE_BYTES;
        #pragma unroll
        for (int j = 0; j < 2; ++j) {
            int idx = tid + (q * 2 + j) * 128;
            int row = idx >> 3, i = idx & 7;
            cpa16(ab + (row * AST + i * 4) * 4,
                  g_Xt + (size_t)s_tok[row] * H2 + k0 + i * 4);
        }
        uint32_t bb = ab + A_BYTES;
        #pragma unroll
        for (int j = 0; j < 2; ++j) {
            int idx = tid + (q * 2 + j) * 128;
            int kr = idx >> 5, i = idx & 31;
            cpa16(bb + (kr * BSTRIDE + i * 4) * 4,
                  wb + (size_t)(k0 + kr) * H + i * 4);
        }
    };

    issue(0, 0); cpa_commit();
    issue(1, 1); cpa_commit();

    float c[4][8][4];
    #pragma unroll
    for (int mi = 0; mi < 4; ++mi)
        #pragma unroll
        for (int ni = 0; ni < 8; ++ni)
            #pragma unroll
            for (int j = 0; j < 4; ++j) c[mi][ni][j] = 0.f;

    const int lane = tid & 31;
    const int grp = lane >> 2, tg = lane & 3;
    const int wid = tid >> 5;
    const int wm = (wid >> 1) * 64;
    const int wn = (wid & 1) * 64;

    unsigned a[2][4][4], b[2][8][2];

    #define LOADF(buf, kk)                                                   \
        { const int k8 = (kk) * 8;                                           \
          _Pragma("unroll")                                                  \
          for (int mi = 0; mi < 4; ++mi) {                                   \
            int r = wm + mi * 16 + grp;                                      \
            a[buf][mi][0] = As[r * AST + k8 + tg];                           \
            a[buf][mi][1] = As[(r + 8) * AST + k8 + tg];                     \
            a[buf][mi][2] = As[r * AST + k8 + tg + 4];                       \
            a[buf][mi][3] = As[(r + 8) * AST + k8 + tg + 4];                 \
          }                                                                  \
          _Pragma("unroll")                                                  \
          for (int ni = 0; ni < 8; ++ni) {                                   \
            int cn = wn + ni * 8 + grp;                                      \
            b[buf][ni][0] = Bs[(k8 + tg) * BSTRIDE + cn];                    \
            b[buf][ni][1] = Bs[(k8 + tg + 4) * BSTRIDE + cn];                \
          } }

    for (int kt = 0; kt < NKT; ++kt) {
        cpa_wait1();
        __syncthreads();

        const unsigned* As = (const unsigned*)(smem + (kt % STG) * STAGE_BYTES);
        const unsigned* Bs = As + BM * AST;
        const int ns = (kt + 2) % STG;
        const bool more = (kt + 2) < NKT;

        LOADF(0, 0);
        #pragma unroll
        for (int kk = 0; kk < 4; ++kk) {
            const int cur = kk & 1;
            if (kk < 3) LOADF(cur ^ 1, kk + 1);     // prefetch next frags
            if (more) issue_q(ns, kt + 2, kk);       // spread next-stage loads
            #pragma unroll
            for (int mi = 0; mi < 4; ++mi)
                #pragma unroll
                for (int ni = 0; ni < 8; ++ni)
                    mma16(c[mi][ni], a[cur][mi], b[cur][ni]);
        }
        cpa_commit();   // one commit per k-tile keeps wait_group(1) aligned
    }
    #undef LOADF

    // epilogue: scale by pair weight, store half2
    #pragma unroll
    for (int mi = 0; mi < 4; ++mi) {
        int rl0 = wm + mi * 16 + grp;
        int rl1 = rl0 + 8;
        float w0 = s_w[rl0], w1 = s_w[rl1];
        #pragma unroll
        for (int ni = 0; ni < 8; ++ni) {
            int colw = (n0 + wn + ni * 8 + tg * 2) >> 1;
            if (mb + rl0 < cnt)
                g_Yp[(size_t)(base + rl0) * H2 + colw] =
                    __floats2half2_rn(c[mi][ni][0] * w0, c[mi][ni][1] * w0);
            if (mb + rl1 < cnt)
                g_Yp[(size_t)(base + rl1) * H2 + colw] =
                    __floats2half2_rn(c[mi][ni][2] * w1, c[mi][ni][3] * w1);
        }
    }
}

// ---------------- combine: out[t] = EPS*sw + sum_k Yp[pos_k] ----------------
__global__ void combine_kernel(float* __restrict__ out, int T) {
    int t = blockIdx.x;
    int c4 = threadIdx.x;
    int b = t * TOPK;
    float bias = EPS * g_sw[t];
    int cw = c4 * 2;

    float4 acc = make_float4(bias, bias, bias, bias);
    #pragma unroll
    for (int k = 0; k < TOPK; ++k) {
        int p = g_pos[b + k];
        uint2 u = *(const uint2*)(g_Yp + (size_t)p * H2 + cw);
        float2 lo = __half22float2(*(__half2*)&u.x);
        float2 hi = __half22float2(*(__half2*)&u.y);
        acc.x += lo.x; acc.y += lo.y; acc.z += hi.x; acc.w += hi.y;
    }
    *(float4*)&out[(size_t)t * H + c4 * 4] = acc;
}

// ---------------- launch ----------------
extern "C" void kernel_launch(void* const* d_in, const int* in_sizes, int n_in,
                              void* d_out, int out_size) {
    const float* tokens = (const float*)d_in[0];
    const float* rw     = (const float*)d_in[1];
    const float* rb     = (const float*)d_in[2];
    const float* ew     = (const float*)d_in[3];
    float* out = (float*)d_out;

    int T = in_sizes[0] / H;   // 8192

    cvt_w_kernel<<<(NEXP * H2 * H + 255) / 256, 256>>>(ew);           // idx 0 (+cursor reset)

    cudaFuncSetAttribute(router_kernel,
                         cudaFuncAttributeMaxDynamicSharedMemorySize, NEXP * H * 4);
    int warps_per_blk = 8;
    int rblocks = (T / 2 + warps_per_blk - 1) / warps_per_blk;
    router_kernel<<<rblocks, warps_per_blk * 32, NEXP * H * 4>>>(tokens, rw, rb, T);  // idx 1

    scan_kernel<<<1, 32>>>();                                         // idx 2

    cudaFuncSetAttribute(gemm_kernel,
                         cudaFuncAttributeMaxDynamicSharedMemorySize, SM_TOTAL);
    dim3 ggrid(H / BN, NTILES_MAX, 1);   // (8, 400): ~384 working tiles
    gemm_kernel<<<ggrid, 128, SM_TOTAL>>>();                          // idx 3 <- profiled

    combine_kernel<<<T, 256>>>(out, T);                               // idx 4
}